// round 14
// baseline (speedup 1.0000x reference)
#include <cuda_runtime.h>
#include <cuda_bf16.h>
#include <cstdint>

#define NT 256

// -------- persistent device scratch (no allocs allowed) --------
__device__ int   g_gmax[1024];      // global max-pool accumulator (float bits, >=0)
__device__ float g_c5[512];         // c5 = b5 + W5[:,64:] @ g

// h (block2 output) as bf16 hi/lo plane images: per 128-pt front CTA,
// [128 rows][36 u32] hi plane (4608 u32) || lo plane (4608 u32)
__device__ __align__(16) uint32_t g_hp[512 * 9216];

// pre-split bf16 weight planes, stored as exact smem slab images (hi plane || lo plane)
__device__ __align__(16) uint32_t g_w2[4608];       // block2: [64][36u32] x2
__device__ __align__(16) uint32_t g_w3[9216];       // block3: [128][36u32] x2
__device__ __align__(16) uint32_t g_w4[16 * 9216];  // block4: 16 slabs [128][36u32] x2
__device__ __align__(16) uint32_t g_w5[8 * 6144];   // block5: 8 slabs [256][12u32] x2
__device__ __align__(16) uint32_t g_w6[32 * 6144];  // block6: 32 slabs [256][12u32] x2
__device__ __align__(16) uint32_t g_w7[4 * 9216];   // block7: 4 slabs [128][36u32] x2 (KF=64)

__device__ __forceinline__ float frelu(float v) { return v > 0.f ? v : 0.f; }

// ============================================================
// HMMA (mma.sync) machinery — compiles at plain sm_103 target.
// ============================================================
__device__ __forceinline__ void mma16816(float* c, const uint32_t* a, const uint32_t* b) {
    asm volatile(
        "mma.sync.aligned.m16n8k16.row.col.f32.bf16.bf16.f32 "
        "{%0,%1,%2,%3}, {%4,%5,%6,%7}, {%8,%9}, {%0,%1,%2,%3};"
        : "+f"(c[0]), "+f"(c[1]), "+f"(c[2]), "+f"(c[3])
        : "r"(a[0]), "r"(a[1]), "r"(a[2]), "r"(a[3]), "r"(b[0]), "r"(b[1]));
}
__device__ __forceinline__ void ldsm4(uint32_t r[4], uint32_t addr) {
    asm volatile("ldmatrix.sync.aligned.m8n8.x4.shared.b16 {%0,%1,%2,%3}, [%4];"
                 : "=r"(r[0]), "=r"(r[1]), "=r"(r[2]), "=r"(r[3]) : "r"(addr));
}
__device__ __forceinline__ uint32_t smem_to_u32(const void* p) {
    uint32_t a;
    asm("{ .reg .u64 t; cvta.to.shared.u64 t, %1; cvt.u32.u64 %0, t; }" : "=r"(a) : "l"(p));
    return a;
}

// ---- cp.async staging (no registers, no STS) ----
__device__ __forceinline__ void cpa16(uint32_t daddr, const void* g) {
    asm volatile("cp.async.cg.shared.global [%0], [%1], 16;" :: "r"(daddr), "l"(g));
}
__device__ __forceinline__ void cpa_commit() {
    asm volatile("cp.async.commit_group;" ::: "memory");
}
__device__ __forceinline__ void cpa_wait0() {
    asm volatile("cp.async.wait_group 0;" ::: "memory");
}
__device__ __forceinline__ void cpa_wait1() {
    asm volatile("cp.async.wait_group 1;" ::: "memory");
}
// copy NV*NT uint4 (NV*NT*4 u32) from src to smem byte-address dbase
template <int NV>
__device__ __forceinline__ void cpaSlab(uint32_t dbase, const uint32_t* __restrict__ src) {
#pragma unroll
    for (int j = 0; j < NV; j++) {
        int idx = threadIdx.x + j * NT;
        cpa16(dbase + (uint32_t)idx * 16, src + (size_t)idx * 4);
    }
}

// split a float2 into packed bf16x2 hi and lo (residual) parts.
__device__ __forceinline__ void split2(float2 v, uint32_t& hi, uint32_t& lo) {
    uint32_t h;
    asm("cvt.rn.bf16x2.f32 %0, %1, %2;" : "=r"(h) : "f"(v.y), "f"(v.x));
    float h0 = __uint_as_float(h << 16);
    float h1 = __uint_as_float(h & 0xFFFF0000u);
    float l0 = v.x - h0, l1 = v.y - h1;
    asm("cvt.rn.bf16x2.f32 %0, %1, %2;" : "=r"(lo) : "f"(l1), "f"(l0));
    hi = h;
}

// ldmatrix.x4 A-fragment load from a bf16 plane (row-major, SAH halves/row).
__device__ __forceinline__ void ldAm(uint32_t r[4], uint32_t plane, int SAH,
                                     int row0, int kabs, int lane) {
    int j = lane >> 3, rr = lane & 7;
    int row = row0 + ((j & 1) << 3) + rr;
    int col = kabs + ((j >> 1) << 3);
    ldsm4(r, plane + (uint32_t)(row * SAH + col) * 2);
}

// One k16 step of warp GEMM on bf16 planes: 32 rows x (NTILES*16) cols, 3-term split.
template <int NTILES>
__device__ __forceinline__ void gemm_kstep_p(uint32_t aHi, uint32_t aLo, int SAH, int m0,
                                             uint32_t whi, uint32_t wlo, int SWB,
                                             int n0loc, int k0loc, int kabs, int lane,
                                             float acc[2][NTILES * 2][4]) {
    uint32_t ahi[2][4], alo[2][4];
    ldAm(ahi[0], aHi, SAH, m0,      kabs, lane);
    ldAm(ahi[1], aHi, SAH, m0 + 16, kabs, lane);
    ldAm(alo[0], aLo, SAH, m0,      kabs, lane);
    ldAm(alo[1], aLo, SAH, m0 + 16, kabs, lane);
    uint32_t bh[NTILES][4], bl[NTILES][4];
    const int nl = n0loc + (lane & 7) + ((lane >> 4) << 3);
    const int kk = k0loc + (((lane >> 3) & 1) << 3);
#pragma unroll
    for (int nt = 0; nt < NTILES; nt++) {
        uint32_t off = (uint32_t)((nl + nt * 16) * SWB + kk) * 2;
        ldsm4(bh[nt], whi + off);
        ldsm4(bl[nt], wlo + off);
    }
#pragma unroll
    for (int mi = 0; mi < 2; mi++)
#pragma unroll
        for (int nt = 0; nt < NTILES; nt++) {
            mma16816(acc[mi][2 * nt],     ahi[mi], &bh[nt][0]);
            mma16816(acc[mi][2 * nt + 1], ahi[mi], &bh[nt][2]);
        }
#pragma unroll
    for (int mi = 0; mi < 2; mi++)
#pragma unroll
        for (int nt = 0; nt < NTILES; nt++) {
            mma16816(acc[mi][2 * nt],     ahi[mi], &bl[nt][0]);
            mma16816(acc[mi][2 * nt + 1], ahi[mi], &bl[nt][2]);
        }
#pragma unroll
    for (int mi = 0; mi < 2; mi++)
#pragma unroll
        for (int nt = 0; nt < NTILES; nt++) {
            mma16816(acc[mi][2 * nt],     alo[mi], &bh[nt][0]);
            mma16816(acc[mi][2 * nt + 1], alo[mi], &bh[nt][2]);
        }
}

// Epilogue: relu(acc + bias) -> bf16 hi/lo planes (u32-addressed, SRU u32/row).
template <int NJ>
__device__ __forceinline__ void epi_store_p(uint32_t* __restrict__ hiP,
                                            uint32_t* __restrict__ loP, int SRU,
                                            int m0, int nbase, const float* __restrict__ bias,
                                            float acc[2][NJ][4], int lane) {
    int g = lane >> 2, t = lane & 3;
#pragma unroll
    for (int mi = 0; mi < 2; mi++)
#pragma unroll
        for (int nj = 0; nj < NJ; nj++) {
            int col = nbase + nj * 8 + 2 * t;
            float2 b = __ldg((const float2*)(bias + col));
            int row = m0 + mi * 16 + g;
            uint32_t h0, l0, h1, l1;
            split2(make_float2(frelu(acc[mi][nj][0] + b.x), frelu(acc[mi][nj][1] + b.y)), h0, l0);
            split2(make_float2(frelu(acc[mi][nj][2] + b.x), frelu(acc[mi][nj][3] + b.y)), h1, l1);
            int cp = col >> 1;
            hiP[row * SRU + cp] = h0;       loP[row * SRU + cp] = l0;
            hiP[(row + 8) * SRU + cp] = h1; loP[(row + 8) * SRU + cp] = l1;
        }
}
// Epilogue: relu(acc + bias) -> fp32 smem (for block7 -> block8)
template <int NJ>
__device__ __forceinline__ void epi_store(float* __restrict__ Z, int SZ, int m0, int nbase,
                                          const float* __restrict__ bias,
                                          float acc[2][NJ][4], int lane) {
    int g = lane >> 2, t = lane & 3;
#pragma unroll
    for (int mi = 0; mi < 2; mi++)
#pragma unroll
        for (int nj = 0; nj < NJ; nj++) {
            int col = nbase + nj * 8 + 2 * t;
            float2 b = __ldg((const float2*)(bias + col));
            int row = m0 + mi * 16 + g;
            *(float2*)(Z + (size_t)row * SZ + col) =
                make_float2(frelu(acc[mi][nj][0] + b.x), frelu(acc[mi][nj][1] + b.y));
            *(float2*)(Z + (size_t)(row + 8) * SZ + col) =
                make_float2(frelu(acc[mi][nj][2] + b.x), frelu(acc[mi][nj][3] + b.y));
        }
}

// ============================================================
// k_prep: split MMA weights into bf16 hi/lo global slab images.
// Also resets g_gmax (merged k_init).
// ============================================================
__global__ void k_prep(const float* __restrict__ W2, const float* __restrict__ W3,
                       const float* __restrict__ W4, const float* __restrict__ W5,
                       const float* __restrict__ W6, const float* __restrict__ W7) {
    const int tid = blockIdx.x * blockDim.x + threadIdx.x;
    const int nth = gridDim.x * blockDim.x;
    if (tid < 1024) g_gmax[tid] = 0;
    // block2: [64 rows][36 u32], K=64
    for (int i = tid; i < 64 * 36; i += nth) {
        int c = i / 36, k2 = i % 36;
        uint32_t hi = 0, lo = 0;
        if (k2 < 32) {
            const float* p = W2 + (size_t)c * 64 + 2 * k2;
            split2(make_float2(p[0], p[1]), hi, lo);
        }
        g_w2[c * 36 + k2] = hi;
        g_w2[2304 + c * 36 + k2] = lo;
    }
    // block3: [128 rows][36 u32], K=64
    for (int i = tid; i < 128 * 36; i += nth) {
        int c = i / 36, k2 = i % 36;
        uint32_t hi = 0, lo = 0;
        if (k2 < 32) {
            const float* p = W3 + (size_t)c * 64 + 2 * k2;
            split2(make_float2(p[0], p[1]), hi, lo);
        }
        g_w3[c * 36 + k2] = hi;
        g_w3[4608 + c * 36 + k2] = lo;
    }
    // block4: 16 slabs [128 rows][36 u32] (KF=64 -> 32 data u32 + 4 pad)
    for (int i = tid; i < 16 * 128 * 36; i += nth) {
        int t = i / (128 * 36), r = i % (128 * 36);
        int c = r / 36, k2 = r % 36;
        uint32_t hi = 0, lo = 0;
        if (k2 < 32) {
            const float* p = W4 + (size_t)((t >> 1) * 128 + c) * 128 + (t & 1) * 64 + 2 * k2;
            split2(make_float2(p[0], p[1]), hi, lo);
        }
        g_w4[t * 9216 + c * 36 + k2] = hi;
        g_w4[t * 9216 + 4608 + c * 36 + k2] = lo;
    }
    // block5: 8 slabs [256][12 u32] (KF=16 -> 8 data + 4 pad)
    for (int i = tid; i < 8 * 256 * 12; i += nth) {
        int t = i / (256 * 12), r = i % (256 * 12);
        int c = r / 12, k2 = r % 12;
        uint32_t hi = 0, lo = 0;
        if (k2 < 8) {
            const float* p = W5 + (size_t)((t >> 2) * 256 + c) * 1088 + (t & 3) * 16 + 2 * k2;
            split2(make_float2(p[0], p[1]), hi, lo);
        }
        g_w5[t * 6144 + c * 12 + k2] = hi;
        g_w5[t * 6144 + 3072 + c * 12 + k2] = lo;
    }
    // block6: 32 slabs [256][12 u32]
    for (int i = tid; i < 32 * 256 * 12; i += nth) {
        int t = i / (256 * 12), r = i % (256 * 12);
        int c = r / 12, k2 = r % 12;
        uint32_t hi = 0, lo = 0;
        if (k2 < 8) {
            const float* p = W6 + (size_t)c * 512 + t * 16 + 2 * k2;
            split2(make_float2(p[0], p[1]), hi, lo);
        }
        g_w6[t * 6144 + c * 12 + k2] = hi;
        g_w6[t * 6144 + 3072 + c * 12 + k2] = lo;
    }
    // block7: 4 slabs [128][36 u32] (KF=64 -> 32 data + 4 pad)
    for (int i = tid; i < 4 * 128 * 36; i += nth) {
        int t = i / (128 * 36), r = i % (128 * 36);
        int c = r / 36, k2 = r % 36;
        uint32_t hi = 0, lo = 0;
        if (k2 < 32) {
            const float* p = W7 + (size_t)c * 256 + t * 64 + 2 * k2;
            split2(make_float2(p[0], p[1]), hi, lo);
        }
        g_w7[t * 9216 + c * 36 + k2] = hi;
        g_w7[t * 9216 + 4608 + c * 36 + k2] = lo;
    }
}

// ============================================================
// Kernel A: block1 SIMT-lite + blocks 2,3,4 via HMMA on bf16 planes.
// CTA = 128 points, 256 threads (4 M-warps x 2 N-warps).
// block4: depth-2 cp.async, 3-buffer ring {w4s, a1/w3 region, h-plane region}.
// ============================================================
#define SMEM1_FLOATS 51328

__global__ __launch_bounds__(NT, 1) void k_front(
    const float* __restrict__ x,
    const float* __restrict__ W1, const float* __restrict__ b1,
    const float* __restrict__ b2, const float* __restrict__ b3,
    const float* __restrict__ b4) {
    extern __shared__ float sm[];
    uint32_t* u = (uint32_t*)sm;
    uint32_t* a1Hi = u;            // SRU 36
    uint32_t* a1Lo = u + 4608;
    uint32_t* w3s  = u;            // overlay (hi @0, lo @4608); later ring slot 1
    uint32_t* hHi  = u + 9216;     // SRU 36; later ring slot 2
    uint32_t* hLo  = u + 13824;
    uint32_t* aHi  = u + 18432;    // SRU 68
    uint32_t* aLo  = u + 27136;
    uint32_t* buf0 = u + 35840;    // ring slot 0 (9216)
    uint32_t* w2s  = u + 45056;    // 4608 (hi 2304 || lo 2304)
    int*   gmax = (int*)(u + 49664);
    float* cst  = sm + 50688;
    float* w1s = cst;          // 192
    float* b1s = cst + 192;    // 64
    float* xs  = cst + 256;    // 384

    const int tid   = threadIdx.x;
    const int wid   = tid >> 5;
    const int lane  = tid & 31;
    const int pbase = blockIdx.x * 128;

    const uint32_t buf4a[3] = { smem_to_u32(buf0), smem_to_u32(u), smem_to_u32(u + 9216) };

    // kick off W4 slab 0 into slot 0 immediately (region untouched until block4)
    cpaSlab<9>(buf4a[0], g_w4);
    cpa_commit();

    for (int i = tid; i < 1024; i += NT) gmax[i] = 0;
    for (int i = tid; i < 192; i += NT) w1s[i] = W1[i];
    for (int i = tid; i < 64; i += NT) b1s[i] = b1[i];
    for (int i = tid; i < 384; i += NT) xs[i] = x[pbase * 3 + i];
    for (int i = tid; i < 1152; i += NT)
        ((uint4*)w2s)[i] = ((const uint4*)g_w2)[i];
    __syncthreads();

    // ---- block1: a1 = relu(x @ W1^T + b1) -> a1 planes
    for (int idx = tid; idx < 128 * 32; idx += NT) {
        int p = idx >> 5, c2 = idx & 31;
        int c = 2 * c2;
        float v0 = fmaf(xs[p * 3 + 2], w1s[c * 3 + 2],
                   fmaf(xs[p * 3 + 1], w1s[c * 3 + 1],
                   fmaf(xs[p * 3 + 0], w1s[c * 3 + 0], b1s[c])));
        float v1 = fmaf(xs[p * 3 + 2], w1s[c * 3 + 5],
                   fmaf(xs[p * 3 + 1], w1s[c * 3 + 4],
                   fmaf(xs[p * 3 + 0], w1s[c * 3 + 3], b1s[c + 1])));
        uint32_t hi, lo;
        split2(make_float2(frelu(v0), frelu(v1)), hi, lo);
        a1Hi[p * 36 + c2] = hi;
        a1Lo[p * 36 + c2] = lo;
    }
    __syncthreads();

    const uint32_t a1Hi_a = smem_to_u32(a1Hi);
    const uint32_t a1Lo_a = smem_to_u32(a1Lo);
    const uint32_t hHi_a  = smem_to_u32(hHi);
    const uint32_t hLo_a  = smem_to_u32(hLo);
    const uint32_t aHi_a  = smem_to_u32(aHi);
    const uint32_t aLo_a  = smem_to_u32(aLo);
    const uint32_t w2hi_a = smem_to_u32(w2s);
    const uint32_t w3hi_a = smem_to_u32(w3s);
    const int m0 = (wid & 3) * 32;   // 4 M-warps
    const int wn = wid >> 2;         // 2 N-warps

    // ---- block2: h = relu(a1 @ W2^T + b2) -> h planes, K=64, N=64 (32 cols/warp)
    {
        float acc[2][4][4];
#pragma unroll
        for (int mi = 0; mi < 2; mi++)
#pragma unroll
            for (int nj = 0; nj < 4; nj++)
#pragma unroll
                for (int q = 0; q < 4; q++) acc[mi][nj][q] = 0.f;
#pragma unroll
        for (int s = 0; s < 4; s++)
            gemm_kstep_p<2>(a1Hi_a, a1Lo_a, 72, m0, w2hi_a, w2hi_a + 2304 * 4, 72,
                            wn * 32, s * 16, s * 16, lane, acc);
        epi_store_p<4>(hHi, hLo, 36, m0, wn * 32, b2, acc, lane);
    }
    __syncthreads();

    // h planes -> global image; w3 image -> smem (a1 dead)
    {
        uint4* dst = (uint4*)(g_hp + (size_t)blockIdx.x * 9216);
        const uint4* srcH = (const uint4*)hHi;
        for (int i = tid; i < 2304; i += NT) dst[i] = srcH[i];
        for (int i = tid; i < 2304; i += NT)
            ((uint4*)w3s)[i] = ((const uint4*)g_w3)[i];
    }
    __syncthreads();

    // ---- block3: a3 = relu(h @ W3^T + b3) -> a planes, K=64, N=128 (64 cols/warp)
    {
        float acc[2][8][4];
#pragma unroll
        for (int mi = 0; mi < 2; mi++)
#pragma unroll
            for (int nj = 0; nj < 8; nj++)
#pragma unroll
                for (int q = 0; q < 4; q++) acc[mi][nj][q] = 0.f;
#pragma unroll
        for (int s = 0; s < 4; s++)
            gemm_kstep_p<4>(hHi_a, hLo_a, 72, m0, w3hi_a, w3hi_a + 4608 * 4, 72,
                            wn * 64, s * 16, s * 16, lane, acc);
        epi_store_p<8>(aHi, aLo, 68, m0, wn * 64, b3, acc, lane);
    }
    __syncthreads();   // w3 reads + h reads done; a-planes written
    cpaSlab<9>(buf4a[1], g_w4 + 9216);   // slab 1 -> ring slot 1 (dead a1/w3)
    cpa_commit();

    // ---- block4: 16 slab-stages (2 per 128-ch chunk), depth-2 pipeline.
    const int n0 = wn * 64;
    for (int cc = 0; cc < 8; cc++) {
        float acc[2][8][4];
#pragma unroll
        for (int mi = 0; mi < 2; mi++)
#pragma unroll
            for (int nj = 0; nj < 8; nj++)
#pragma unroll
                for (int q = 0; q < 4; q++) acc[mi][nj][q] = 0.f;

        for (int s = 0; s < 2; s++) {
            int t = cc * 2 + s;
            if (t < 15) cpa_wait1(); else cpa_wait0();
            __syncthreads();
            if (t + 2 < 16) { cpaSlab<9>(buf4a[(t + 2) % 3], g_w4 + (t + 2) * 9216); cpa_commit(); }
            uint32_t whi = buf4a[t % 3];
#pragma unroll
            for (int q = 0; q < 4; q++)
                gemm_kstep_p<4>(aHi_a, aLo_a, 136, m0, whi, whi + 4608 * 4, 72,
                                n0, q * 16, s * 64 + q * 16, lane, acc);
        }

        float m0v[8], m1v[8];
#pragma unroll
        for (int nj = 0; nj < 8; nj++) {
            m0v[nj] = fmaxf(fmaxf(acc[0][nj][0], acc[0][nj][2]),
                            fmaxf(acc[1][nj][0], acc[1][nj][2]));
            m1v[nj] = fmaxf(fmaxf(acc[0][nj][1], acc[0][nj][3]),
                            fmaxf(acc[1][nj][1], acc[1][nj][3]));
        }
#pragma unroll
        for (int m = 4; m < 32; m <<= 1)
#pragma unroll
            for (int nj = 0; nj < 8; nj++) {
                m0v[nj] = fmaxf(m0v[nj], __shfl_xor_sync(0xffffffffu, m0v[nj], m));
                m1v[nj] = fmaxf(m1v[nj], __shfl_xor_sync(0xffffffffu, m1v[nj], m));
            }
        if ((lane >> 2) == 0) {
            int t = lane & 3;
#pragma unroll
            for (int nj = 0; nj < 8; nj++) {
                int col = cc * 128 + n0 + nj * 8 + 2 * t;
                float2 b = __ldg((const float2*)(b4 + col));
                atomicMax(&gmax[col],     __float_as_int(frelu(m0v[nj] + b.x)));
                atomicMax(&gmax[col + 1], __float_as_int(frelu(m1v[nj] + b.y)));
            }
        }
    }
    __syncthreads();
    for (int i = tid; i < 1024; i += NT) atomicMax(&g_gmax[i], gmax[i]);
}

// ============================================================
// Kernel B: c5[j] = b5[j] + sum_i W5[j][64+i] * g[i]
// ============================================================
__global__ void k_c5(const float* __restrict__ W5, const float* __restrict__ b5) {
    __shared__ float gs[1024];
    const int tid = threadIdx.x;
    for (int i = tid; i < 1024; i += 256) gs[i] = __int_as_float(g_gmax[i]);
    __syncthreads();
    const int w = tid >> 5, lane = tid & 31;
    const int j = blockIdx.x * 8 + w;
    const float* wr = W5 + (size_t)j * 1088 + 64;
    float s = 0.f;
#pragma unroll
    for (int i = 0; i < 32; i++) s = fmaf(wr[lane + 32 * i], gs[lane + 32 * i], s);
#pragma unroll
    for (int m = 16; m; m >>= 1) s += __shfl_xor_sync(0xffffffffu, s, m);
    if (lane == 0) g_c5[j] = s + b5[j];
}

// ============================================================
// Kernel C: blocks 5..8 via HMMA on bf16 planes. depth-2 cp.async.
// CTA = 64 pts, 256 threads (2 M-warps x 4 N-warps).
// Rings: block5 {whi32, z6+4608, z6+10752} (h planes live at z6..4608)
//        block6 {whi32, z6Hi, z6Hi+6144}  (h dead)
//        block7 {z5Hi, z5Hi+9216, z5Hi+18432} (z5 dead)
// ============================================================
#define SMEM3_FLOATS 56320

__global__ __launch_bounds__(NT, 1) void k_back(
    const float* __restrict__ b6, const float* __restrict__ b7,
    const float* __restrict__ W8, const float* __restrict__ b8,
    float* __restrict__ out) {
    extern __shared__ float sm[];
    uint32_t* z5Hi = (uint32_t*)sm;           // 16640 u32, SAH=520 (SRU=260)
    uint32_t* z5Lo = z5Hi + 16640;
    uint32_t* z6Hi = (uint32_t*)(sm + 33280); // 8448 u32, SAH=264 (SRU=132)
    uint32_t* z6Lo = z6Hi + 8448;
    uint32_t* hHi  = z6Hi;                    // overlay: 2304 u32, SAH=72 (SRU=36)
    uint32_t* hLo  = hHi + 2304;
    uint32_t* whi32 = (uint32_t*)(sm + 50176); // buffer region (6144)
    float* z7 = sm;                           // stride 132 (overlays z5 planes)

    const int tid   = threadIdx.x;
    const int wid   = tid >> 5;
    const int lane  = tid & 31;
    const int pbase = blockIdx.x * 64;

    const uint32_t z5Hi_a = smem_to_u32(z5Hi);
    const uint32_t z5Lo_a = smem_to_u32(z5Lo);
    const uint32_t z6Hi_a = smem_to_u32(z6Hi);
    const uint32_t z6Lo_a = smem_to_u32(z6Lo);
    const uint32_t hHi_a  = smem_to_u32(hHi);
    const uint32_t hLo_a  = smem_to_u32(hLo);
    const uint32_t whi_a  = smem_to_u32(whi32);
    const uint32_t buf5a[3] = { whi_a, z6Hi_a + 4608 * 4, z6Hi_a + 10752 * 4 };
    const uint32_t buf6a[3] = { whi_a, z6Hi_a, z6Hi_a + 6144 * 4 };
    const uint32_t buf7a[3] = { z5Hi_a, z5Hi_a + 9216 * 4, z5Hi_a + 18432 * 4 };

    // pre-issue W5 slabs 0,1 (regions free: whi32, z6+4608..)
    cpaSlab<6>(buf5a[0], g_w5);          cpa_commit();
    cpaSlab<6>(buf5a[1], g_w5 + 6144);   cpa_commit();

    // copy h planes from pre-split global image
    {
        const uint32_t* hiSrc = g_hp + (size_t)(blockIdx.x >> 1) * 9216 + (blockIdx.x & 1) * 2304;
        const uint4* s0 = (const uint4*)hiSrc;
        const uint4* s1 = (const uint4*)(hiSrc + 4608);
        uint4* d0 = (uint4*)hHi;
        uint4* d1 = (uint4*)hLo;
        for (int i = tid; i < 576; i += NT) { d0[i] = s0[i]; d1[i] = s1[i]; }
    }

    const int m0 = (wid & 1) * 32;   // 2 M-warps
    const int wn = wid >> 1;         // 4 N-warps

    // ---- block5: z5 = relu(h @ W5a^T + c5). 8 stages, epi after t=3,7.
    for (int cc = 0; cc < 2; cc++) {
        float acc[2][8][4];
#pragma unroll
        for (int mi = 0; mi < 2; mi++)
#pragma unroll
            for (int nj = 0; nj < 8; nj++)
#pragma unroll
                for (int q = 0; q < 4; q++) acc[mi][nj][q] = 0.f;
        for (int s = 0; s < 4; s++) {
            int t = cc * 4 + s;
            if (t < 7) cpa_wait1(); else cpa_wait0();
            __syncthreads();
            if (t + 2 < 8) { cpaSlab<6>(buf5a[(t + 2) % 3], g_w5 + (t + 2) * 6144); cpa_commit(); }
            uint32_t whi = buf5a[t % 3];
            gemm_kstep_p<4>(hHi_a, hLo_a, 72, m0, whi, whi + 3072 * 4, 24,
                            wn * 64, 0, s * 16, lane, acc);
        }
        epi_store_p<8>(z5Hi, z5Lo, 260, m0, cc * 256 + wn * 64, g_c5, acc, lane);
    }
    __syncthreads();   // block5 reads done (h dead); epi z5 writes visible
    cpaSlab<6>(buf6a[0], g_w6);          cpa_commit();
    cpaSlab<6>(buf6a[1], g_w6 + 6144);   cpa_commit();

    // ---- block6: z6 = relu(z5 @ W6^T + b6). 32 stages, depth-2 pipeline.
    {
        float acc[2][8][4];
#pragma unroll
        for (int mi = 0; mi < 2; mi++)
#pragma unroll
            for (int nj = 0; nj < 8; nj++)
#pragma unroll
                for (int q = 0; q < 4; q++) acc[mi][nj][q] = 0.f;
        for (int s = 0; s < 32; s++) {
            if (s < 31) cpa_wait1(); else cpa_wait0();
            __syncthreads();
            if (s + 2 < 32) { cpaSlab<6>(buf6a[(s + 2) % 3], g_w6 + (s + 2) * 6144); cpa_commit(); }
            uint32_t whi = buf6a[s % 3];
            gemm_kstep_p<4>(z5Hi_a, z5Lo_a, 520, m0, whi, whi + 3072 * 4, 24,
                            wn * 64, 0, s * 16, lane, acc);
        }
        __syncthreads();   // all buffer + z5 reads done
        cpaSlab<9>(buf7a[0], g_w7);          cpa_commit();   // into dead z5 region
        cpaSlab<9>(buf7a[1], g_w7 + 9216);   cpa_commit();
        epi_store_p<8>(z6Hi, z6Lo, 132, m0, wn * 64, b6, acc, lane);
    }

    // ---- block7: z7 = relu(z6 @ W7^T + b7). 4 stages of KF=64, depth-2.
    {
        float acc[2][4][4];
#pragma unroll
        for (int mi = 0; mi < 2; mi++)
#pragma unroll
            for (int nj = 0; nj < 4; nj++)
#pragma unroll
                for (int q = 0; q < 4; q++) acc[mi][nj][q] = 0.f;
        for (int s = 0; s < 4; s++) {
            if (s < 3) cpa_wait1(); else cpa_wait0();
            __syncthreads();   // stage-0 sync also orders z6 epilogue before gemm
            if (s + 2 < 4) { cpaSlab<9>(buf7a[(s + 2) % 3], g_w7 + (s + 2) * 9216); cpa_commit(); }
            uint32_t whi = buf7a[s % 3];
#pragma unroll
            for (int q = 0; q < 4; q++)
                gemm_kstep_p<2>(z6Hi_a, z6Lo_a, 264, m0, whi, whi + 4608 * 4, 72,
                                wn * 32, q * 16, s * 64 + q * 16, lane, acc);
        }
        __syncthreads();   // all ring reads done; safe to overlay z7 fp32
        epi_store<4>(z7, 132, m0, wn * 32, b7, acc, lane);
    }
    __syncthreads();

    // ---- block8: out = z7 @ W8^T + b8 (no relu)
    if (tid < 64) {
        const float* zr = z7 + tid * 132;
        float s = __ldg(b8);
#pragma unroll 8
        for (int k = 0; k < 128; k++) s = fmaf(zr[k], __ldg(W8 + k), s);
        out[pbase + tid] = s;
    }
}

// ============================================================
extern "C" void kernel_launch(void* const* d_in, const int* in_sizes, int n_in,
                              void* d_out, int out_size) {
    const float* x  = (const float*)d_in[0];
    const float* W1 = (const float*)d_in[1];  const float* b1 = (const float*)d_in[2];
    const float* W2 = (const float*)d_in[3];  const float* b2 = (const float*)d_in[4];
    const float* W3 = (const float*)d_in[5];  const float* b3 = (const float*)d_in[6];
    const float* W4 = (const float*)d_in[7];  const float* b4 = (const float*)d_in[8];
    const float* W5 = (const float*)d_in[9];  const float* b5 = (const float*)d_in[10];
    const float* W6 = (const float*)d_in[11]; const float* b6 = (const float*)d_in[12];
    const float* W7 = (const float*)d_in[13]; const float* b7 = (const float*)d_in[14];
    const float* W8 = (const float*)d_in[15]; const float* b8 = (const float*)d_in[16];
    float* out = (float*)d_out;

    const int n = in_sizes[0] / 3;  // 65536

    const int smem1 = SMEM1_FLOATS * (int)sizeof(float);
    const int smem3 = SMEM3_FLOATS * (int)sizeof(float);
    cudaFuncSetAttribute(k_front, cudaFuncAttributeMaxDynamicSharedMemorySize, smem1);
    cudaFuncSetAttribute(k_back,  cudaFuncAttributeMaxDynamicSharedMemorySize, smem3);

    k_prep<<<128, 256>>>(W2, W3, W4, W5, W6, W7);
    k_front<<<n / 128, NT, smem1>>>(x, W1, b1, b2, b3, b4);
    k_c5<<<64, 256>>>(W5, b5);
    k_back<<<n / 64, NT, smem3>>>(b6, b7, W8, b8, out);
}

// round 15
// speedup vs baseline: 1.0504x; 1.0504x over previous
#include <cuda_runtime.h>
#include <cuda_bf16.h>
#include <cstdint>

#define NT 256

// -------- persistent device scratch (no allocs allowed) --------
__device__ int   g_gmax[1024];      // global max-pool accumulator (float bits, >=0)
__device__ float g_c5[512];         // c5 = b5 + W5[:,64:] @ g

// h (block2 output) as bf16 hi/lo plane images: per 128-pt front CTA,
// [128 rows][36 u32] hi plane (4608 u32) || lo plane (4608 u32)
__device__ __align__(16) uint32_t g_hp[512 * 9216];

// pre-split bf16 weight planes, stored as exact smem slab images (hi plane || lo plane)
__device__ __align__(16) uint32_t g_w2[4608];       // block2: [64][36u32] x2
__device__ __align__(16) uint32_t g_w3[9216];       // block3: [128][36u32] x2
__device__ __align__(16) uint32_t g_w4[16 * 9216];  // block4: 16 slabs [128][36u32] x2
__device__ __align__(16) uint32_t g_w5[8 * 6144];   // block5: 8 slabs [256][12u32] x2
__device__ __align__(16) uint32_t g_w6[32 * 6144];  // block6: 32 slabs [256][12u32] x2
__device__ __align__(16) uint32_t g_w7[4 * 9216];   // block7: 4 slabs [128][36u32] x2 (KF=64)

__device__ __forceinline__ float frelu(float v) { return v > 0.f ? v : 0.f; }

// ============================================================
// HMMA (mma.sync) machinery — compiles at plain sm_103 target.
// ============================================================
__device__ __forceinline__ void mma16816(float* c, const uint32_t* a, const uint32_t* b) {
    asm volatile(
        "mma.sync.aligned.m16n8k16.row.col.f32.bf16.bf16.f32 "
        "{%0,%1,%2,%3}, {%4,%5,%6,%7}, {%8,%9}, {%0,%1,%2,%3};"
        : "+f"(c[0]), "+f"(c[1]), "+f"(c[2]), "+f"(c[3])
        : "r"(a[0]), "r"(a[1]), "r"(a[2]), "r"(a[3]), "r"(b[0]), "r"(b[1]));
}
__device__ __forceinline__ void ldsm4(uint32_t r[4], uint32_t addr) {
    asm volatile("ldmatrix.sync.aligned.m8n8.x4.shared.b16 {%0,%1,%2,%3}, [%4];"
                 : "=r"(r[0]), "=r"(r[1]), "=r"(r[2]), "=r"(r[3]) : "r"(addr));
}
__device__ __forceinline__ uint32_t smem_to_u32(const void* p) {
    uint32_t a;
    asm("{ .reg .u64 t; cvta.to.shared.u64 t, %1; cvt.u32.u64 %0, t; }" : "=r"(a) : "l"(p));
    return a;
}

// ---- cp.async staging (no registers, no STS) ----
__device__ __forceinline__ void cpa16(uint32_t daddr, const void* g) {
    asm volatile("cp.async.cg.shared.global [%0], [%1], 16;" :: "r"(daddr), "l"(g));
}
__device__ __forceinline__ void cpa_commit() {
    asm volatile("cp.async.commit_group;" ::: "memory");
}
__device__ __forceinline__ void cpa_wait0() {
    asm volatile("cp.async.wait_group 0;" ::: "memory");
}
// copy NV*NT uint4 (NV*NT*4 u32) from src to smem byte-address dbase
template <int NV>
__device__ __forceinline__ void cpaSlab(uint32_t dbase, const uint32_t* __restrict__ src) {
#pragma unroll
    for (int j = 0; j < NV; j++) {
        int idx = threadIdx.x + j * NT;
        cpa16(dbase + (uint32_t)idx * 16, src + (size_t)idx * 4);
    }
}

// split a float2 into packed bf16x2 hi and lo (residual) parts.
__device__ __forceinline__ void split2(float2 v, uint32_t& hi, uint32_t& lo) {
    uint32_t h;
    asm("cvt.rn.bf16x2.f32 %0, %1, %2;" : "=r"(h) : "f"(v.y), "f"(v.x));
    float h0 = __uint_as_float(h << 16);
    float h1 = __uint_as_float(h & 0xFFFF0000u);
    float l0 = v.x - h0, l1 = v.y - h1;
    asm("cvt.rn.bf16x2.f32 %0, %1, %2;" : "=r"(lo) : "f"(l1), "f"(l0));
    hi = h;
}

// ldmatrix.x4 A-fragment load from a bf16 plane (row-major, SAH halves/row).
__device__ __forceinline__ void ldAm(uint32_t r[4], uint32_t plane, int SAH,
                                     int row0, int kabs, int lane) {
    int j = lane >> 3, rr = lane & 7;
    int row = row0 + ((j & 1) << 3) + rr;
    int col = kabs + ((j >> 1) << 3);
    ldsm4(r, plane + (uint32_t)(row * SAH + col) * 2);
}

// One k16 step of warp GEMM on bf16 planes: 32 rows x (NTILES*16) cols, 3-term split.
template <int NTILES>
__device__ __forceinline__ void gemm_kstep_p(uint32_t aHi, uint32_t aLo, int SAH, int m0,
                                             uint32_t whi, uint32_t wlo, int SWB,
                                             int n0loc, int k0loc, int kabs, int lane,
                                             float acc[2][NTILES * 2][4]) {
    uint32_t ahi[2][4], alo[2][4];
    ldAm(ahi[0], aHi, SAH, m0,      kabs, lane);
    ldAm(ahi[1], aHi, SAH, m0 + 16, kabs, lane);
    ldAm(alo[0], aLo, SAH, m0,      kabs, lane);
    ldAm(alo[1], aLo, SAH, m0 + 16, kabs, lane);
    uint32_t bh[NTILES][4], bl[NTILES][4];
    const int nl = n0loc + (lane & 7) + ((lane >> 4) << 3);
    const int kk = k0loc + (((lane >> 3) & 1) << 3);
#pragma unroll
    for (int nt = 0; nt < NTILES; nt++) {
        uint32_t off = (uint32_t)((nl + nt * 16) * SWB + kk) * 2;
        ldsm4(bh[nt], whi + off);
        ldsm4(bl[nt], wlo + off);
    }
#pragma unroll
    for (int mi = 0; mi < 2; mi++)
#pragma unroll
        for (int nt = 0; nt < NTILES; nt++) {
            mma16816(acc[mi][2 * nt],     ahi[mi], &bh[nt][0]);
            mma16816(acc[mi][2 * nt + 1], ahi[mi], &bh[nt][2]);
        }
#pragma unroll
    for (int mi = 0; mi < 2; mi++)
#pragma unroll
        for (int nt = 0; nt < NTILES; nt++) {
            mma16816(acc[mi][2 * nt],     ahi[mi], &bl[nt][0]);
            mma16816(acc[mi][2 * nt + 1], ahi[mi], &bl[nt][2]);
        }
#pragma unroll
    for (int mi = 0; mi < 2; mi++)
#pragma unroll
        for (int nt = 0; nt < NTILES; nt++) {
            mma16816(acc[mi][2 * nt],     alo[mi], &bh[nt][0]);
            mma16816(acc[mi][2 * nt + 1], alo[mi], &bh[nt][2]);
        }
}

// Epilogue: relu(acc + bias) -> bf16 hi/lo planes (u32-addressed, SRU u32/row).
template <int NJ>
__device__ __forceinline__ void epi_store_p(uint32_t* __restrict__ hiP,
                                            uint32_t* __restrict__ loP, int SRU,
                                            int m0, int nbase, const float* __restrict__ bias,
                                            float acc[2][NJ][4], int lane) {
    int g = lane >> 2, t = lane & 3;
#pragma unroll
    for (int mi = 0; mi < 2; mi++)
#pragma unroll
        for (int nj = 0; nj < NJ; nj++) {
            int col = nbase + nj * 8 + 2 * t;
            float2 b = __ldg((const float2*)(bias + col));
            int row = m0 + mi * 16 + g;
            uint32_t h0, l0, h1, l1;
            split2(make_float2(frelu(acc[mi][nj][0] + b.x), frelu(acc[mi][nj][1] + b.y)), h0, l0);
            split2(make_float2(frelu(acc[mi][nj][2] + b.x), frelu(acc[mi][nj][3] + b.y)), h1, l1);
            int cp = col >> 1;
            hiP[row * SRU + cp] = h0;       loP[row * SRU + cp] = l0;
            hiP[(row + 8) * SRU + cp] = h1; loP[(row + 8) * SRU + cp] = l1;
        }
}
// Epilogue: relu(acc + bias) -> fp32 smem (for block7 -> block8)
template <int NJ>
__device__ __forceinline__ void epi_store(float* __restrict__ Z, int SZ, int m0, int nbase,
                                          const float* __restrict__ bias,
                                          float acc[2][NJ][4], int lane) {
    int g = lane >> 2, t = lane & 3;
#pragma unroll
    for (int mi = 0; mi < 2; mi++)
#pragma unroll
        for (int nj = 0; nj < NJ; nj++) {
            int col = nbase + nj * 8 + 2 * t;
            float2 b = __ldg((const float2*)(bias + col));
            int row = m0 + mi * 16 + g;
            *(float2*)(Z + (size_t)row * SZ + col) =
                make_float2(frelu(acc[mi][nj][0] + b.x), frelu(acc[mi][nj][1] + b.y));
            *(float2*)(Z + (size_t)(row + 8) * SZ + col) =
                make_float2(frelu(acc[mi][nj][2] + b.x), frelu(acc[mi][nj][3] + b.y));
        }
}

// ============================================================
// k_prep: split MMA weights into bf16 hi/lo global slab images.
// Also resets g_gmax (merged k_init).
// ============================================================
__global__ void k_prep(const float* __restrict__ W2, const float* __restrict__ W3,
                       const float* __restrict__ W4, const float* __restrict__ W5,
                       const float* __restrict__ W6, const float* __restrict__ W7) {
    const int tid = blockIdx.x * blockDim.x + threadIdx.x;
    const int nth = gridDim.x * blockDim.x;
    if (tid < 1024) g_gmax[tid] = 0;
    // block2: [64 rows][36 u32], K=64
    for (int i = tid; i < 64 * 36; i += nth) {
        int c = i / 36, k2 = i % 36;
        uint32_t hi = 0, lo = 0;
        if (k2 < 32) {
            const float* p = W2 + (size_t)c * 64 + 2 * k2;
            split2(make_float2(p[0], p[1]), hi, lo);
        }
        g_w2[c * 36 + k2] = hi;
        g_w2[2304 + c * 36 + k2] = lo;
    }
    // block3: [128 rows][36 u32], K=64
    for (int i = tid; i < 128 * 36; i += nth) {
        int c = i / 36, k2 = i % 36;
        uint32_t hi = 0, lo = 0;
        if (k2 < 32) {
            const float* p = W3 + (size_t)c * 64 + 2 * k2;
            split2(make_float2(p[0], p[1]), hi, lo);
        }
        g_w3[c * 36 + k2] = hi;
        g_w3[4608 + c * 36 + k2] = lo;
    }
    // block4: 16 slabs [128 rows][36 u32] (KF=64 -> 32 data u32 + 4 pad)
    for (int i = tid; i < 16 * 128 * 36; i += nth) {
        int t = i / (128 * 36), r = i % (128 * 36);
        int c = r / 36, k2 = r % 36;
        uint32_t hi = 0, lo = 0;
        if (k2 < 32) {
            const float* p = W4 + (size_t)((t >> 1) * 128 + c) * 128 + (t & 1) * 64 + 2 * k2;
            split2(make_float2(p[0], p[1]), hi, lo);
        }
        g_w4[t * 9216 + c * 36 + k2] = hi;
        g_w4[t * 9216 + 4608 + c * 36 + k2] = lo;
    }
    // block5: 8 slabs [256][12 u32] (KF=16 -> 8 data + 4 pad)
    for (int i = tid; i < 8 * 256 * 12; i += nth) {
        int t = i / (256 * 12), r = i % (256 * 12);
        int c = r / 12, k2 = r % 12;
        uint32_t hi = 0, lo = 0;
        if (k2 < 8) {
            const float* p = W5 + (size_t)((t >> 2) * 256 + c) * 1088 + (t & 3) * 16 + 2 * k2;
            split2(make_float2(p[0], p[1]), hi, lo);
        }
        g_w5[t * 6144 + c * 12 + k2] = hi;
        g_w5[t * 6144 + 3072 + c * 12 + k2] = lo;
    }
    // block6: 32 slabs [256][12 u32]
    for (int i = tid; i < 32 * 256 * 12; i += nth) {
        int t = i / (256 * 12), r = i % (256 * 12);
        int c = r / 12, k2 = r % 12;
        uint32_t hi = 0, lo = 0;
        if (k2 < 8) {
            const float* p = W6 + (size_t)c * 512 + t * 16 + 2 * k2;
            split2(make_float2(p[0], p[1]), hi, lo);
        }
        g_w6[t * 6144 + c * 12 + k2] = hi;
        g_w6[t * 6144 + 3072 + c * 12 + k2] = lo;
    }
    // block7: 4 slabs [128][36 u32] (KF=64 -> 32 data + 4 pad)
    for (int i = tid; i < 4 * 128 * 36; i += nth) {
        int t = i / (128 * 36), r = i % (128 * 36);
        int c = r / 36, k2 = r % 36;
        uint32_t hi = 0, lo = 0;
        if (k2 < 32) {
            const float* p = W7 + (size_t)c * 256 + t * 64 + 2 * k2;
            split2(make_float2(p[0], p[1]), hi, lo);
        }
        g_w7[t * 9216 + c * 36 + k2] = hi;
        g_w7[t * 9216 + 4608 + c * 36 + k2] = lo;
    }
}

// ============================================================
// Kernel A: block1 SIMT-lite + blocks 2,3,4 via HMMA on bf16 planes.
// CTA = 128 points, 256 threads (4 M-warps x 2 N-warps).
// block4: cp.async ping-pong, buf0 = w4s region, buf1 = a1/w3 region.
// ============================================================
#define SMEM1_FLOATS 51328

__global__ __launch_bounds__(NT, 1) void k_front(
    const float* __restrict__ x,
    const float* __restrict__ W1, const float* __restrict__ b1,
    const float* __restrict__ b2, const float* __restrict__ b3,
    const float* __restrict__ b4) {
    extern __shared__ float sm[];
    uint32_t* u = (uint32_t*)sm;
    uint32_t* a1Hi = u;            // SRU 36
    uint32_t* a1Lo = u + 4608;
    uint32_t* w3s  = u;            // overlay (hi @0, lo @4608); later buf1
    uint32_t* hHi  = u + 9216;     // SRU 36
    uint32_t* hLo  = u + 13824;
    uint32_t* aHi  = u + 18432;    // SRU 68
    uint32_t* aLo  = u + 27136;
    uint32_t* buf0 = u + 35840;    // block4 buffer 0 (9216)
    uint32_t* w2s  = u + 45056;    // 4608 (hi 2304 || lo 2304)
    int*   gmax = (int*)(u + 49664);
    float* cst  = sm + 50688;
    float* w1s = cst;          // 192
    float* b1s = cst + 192;    // 64
    float* xs  = cst + 256;    // 384

    const int tid   = threadIdx.x;
    const int wid   = tid >> 5;
    const int lane  = tid & 31;
    const int pbase = blockIdx.x * 128;

    const uint32_t buf4a[2] = { smem_to_u32(buf0), smem_to_u32(u) };  // buf1 = a1/w3 region

    // kick off W4 slab 0 into buf0 immediately (region untouched until block4)
    cpaSlab<9>(buf4a[0], g_w4);
    cpa_commit();

    for (int i = tid; i < 1024; i += NT) gmax[i] = 0;
    for (int i = tid; i < 192; i += NT) w1s[i] = W1[i];
    for (int i = tid; i < 64; i += NT) b1s[i] = b1[i];
    for (int i = tid; i < 384; i += NT) xs[i] = x[pbase * 3 + i];
    for (int i = tid; i < 1152; i += NT)
        ((uint4*)w2s)[i] = ((const uint4*)g_w2)[i];
    __syncthreads();

    // ---- block1: a1 = relu(x @ W1^T + b1) -> a1 planes
    for (int idx = tid; idx < 128 * 32; idx += NT) {
        int p = idx >> 5, c2 = idx & 31;
        int c = 2 * c2;
        float v0 = fmaf(xs[p * 3 + 2], w1s[c * 3 + 2],
                   fmaf(xs[p * 3 + 1], w1s[c * 3 + 1],
                   fmaf(xs[p * 3 + 0], w1s[c * 3 + 0], b1s[c])));
        float v1 = fmaf(xs[p * 3 + 2], w1s[c * 3 + 5],
                   fmaf(xs[p * 3 + 1], w1s[c * 3 + 4],
                   fmaf(xs[p * 3 + 0], w1s[c * 3 + 3], b1s[c + 1])));
        uint32_t hi, lo;
        split2(make_float2(frelu(v0), frelu(v1)), hi, lo);
        a1Hi[p * 36 + c2] = hi;
        a1Lo[p * 36 + c2] = lo;
    }
    __syncthreads();

    const uint32_t a1Hi_a = smem_to_u32(a1Hi);
    const uint32_t a1Lo_a = smem_to_u32(a1Lo);
    const uint32_t hHi_a  = smem_to_u32(hHi);
    const uint32_t hLo_a  = smem_to_u32(hLo);
    const uint32_t aHi_a  = smem_to_u32(aHi);
    const uint32_t aLo_a  = smem_to_u32(aLo);
    const uint32_t w2hi_a = smem_to_u32(w2s);
    const uint32_t w3hi_a = smem_to_u32(w3s);
    const int m0 = (wid & 3) * 32;   // 4 M-warps
    const int wn = wid >> 2;         // 2 N-warps

    // ---- block2: h = relu(a1 @ W2^T + b2) -> h planes, K=64, N=64 (32 cols/warp)
    {
        float acc[2][4][4];
#pragma unroll
        for (int mi = 0; mi < 2; mi++)
#pragma unroll
            for (int nj = 0; nj < 4; nj++)
#pragma unroll
                for (int q = 0; q < 4; q++) acc[mi][nj][q] = 0.f;
#pragma unroll
        for (int s = 0; s < 4; s++)
            gemm_kstep_p<2>(a1Hi_a, a1Lo_a, 72, m0, w2hi_a, w2hi_a + 2304 * 4, 72,
                            wn * 32, s * 16, s * 16, lane, acc);
        epi_store_p<4>(hHi, hLo, 36, m0, wn * 32, b2, acc, lane);
    }
    __syncthreads();

    // h planes -> global image; w3 image -> smem (a1 dead)
    {
        uint4* dst = (uint4*)(g_hp + (size_t)blockIdx.x * 9216);
        const uint4* srcH = (const uint4*)hHi;
        for (int i = tid; i < 2304; i += NT) dst[i] = srcH[i];
        for (int i = tid; i < 2304; i += NT)
            ((uint4*)w3s)[i] = ((const uint4*)g_w3)[i];
    }
    __syncthreads();

    // ---- block3: a3 = relu(h @ W3^T + b3) -> a planes, K=64, N=128 (64 cols/warp)
    {
        float acc[2][8][4];
#pragma unroll
        for (int mi = 0; mi < 2; mi++)
#pragma unroll
            for (int nj = 0; nj < 8; nj++)
#pragma unroll
                for (int q = 0; q < 4; q++) acc[mi][nj][q] = 0.f;
#pragma unroll
        for (int s = 0; s < 4; s++)
            gemm_kstep_p<4>(hHi_a, hLo_a, 72, m0, w3hi_a, w3hi_a + 4608 * 4, 72,
                            wn * 64, s * 16, s * 16, lane, acc);
        epi_store_p<8>(aHi, aLo, 68, m0, wn * 64, b3, acc, lane);
    }
    // no sync — block4 stage 0's sync orders epi writes and w3 reads.

    // ---- block4: 16 slab-stages (2 per 128-ch chunk), cp.async ping-pong.
    const int n0 = wn * 64;
    for (int cc = 0; cc < 8; cc++) {
        float acc[2][8][4];
#pragma unroll
        for (int mi = 0; mi < 2; mi++)
#pragma unroll
            for (int nj = 0; nj < 8; nj++)
#pragma unroll
                for (int q = 0; q < 4; q++) acc[mi][nj][q] = 0.f;

        for (int s = 0; s < 2; s++) {
            int t = cc * 2 + s;
            cpa_wait0();
            __syncthreads();
            if (t + 1 < 16) { cpaSlab<9>(buf4a[(t + 1) & 1], g_w4 + (t + 1) * 9216); cpa_commit(); }
            uint32_t whi = buf4a[t & 1];
#pragma unroll
            for (int q = 0; q < 4; q++)
                gemm_kstep_p<4>(aHi_a, aLo_a, 136, m0, whi, whi + 4608 * 4, 72,
                                n0, q * 16, s * 64 + q * 16, lane, acc);
        }

        float m0v[8], m1v[8];
#pragma unroll
        for (int nj = 0; nj < 8; nj++) {
            m0v[nj] = fmaxf(fmaxf(acc[0][nj][0], acc[0][nj][2]),
                            fmaxf(acc[1][nj][0], acc[1][nj][2]));
            m1v[nj] = fmaxf(fmaxf(acc[0][nj][1], acc[0][nj][3]),
                            fmaxf(acc[1][nj][1], acc[1][nj][3]));
        }
#pragma unroll
        for (int m = 4; m < 32; m <<= 1)
#pragma unroll
            for (int nj = 0; nj < 8; nj++) {
                m0v[nj] = fmaxf(m0v[nj], __shfl_xor_sync(0xffffffffu, m0v[nj], m));
                m1v[nj] = fmaxf(m1v[nj], __shfl_xor_sync(0xffffffffu, m1v[nj], m));
            }
        if ((lane >> 2) == 0) {
            int t = lane & 3;
#pragma unroll
            for (int nj = 0; nj < 8; nj++) {
                int col = cc * 128 + n0 + nj * 8 + 2 * t;
                float2 b = __ldg((const float2*)(b4 + col));
                atomicMax(&gmax[col],     __float_as_int(frelu(m0v[nj] + b.x)));
                atomicMax(&gmax[col + 1], __float_as_int(frelu(m1v[nj] + b.y)));
            }
        }
    }
    __syncthreads();
    for (int i = tid; i < 1024; i += NT) atomicMax(&g_gmax[i], gmax[i]);
}

// ============================================================
// Kernel B: c5[j] = b5[j] + sum_i W5[j][64+i] * g[i]
// ============================================================
__global__ void k_c5(const float* __restrict__ W5, const float* __restrict__ b5) {
    __shared__ float gs[1024];
    const int tid = threadIdx.x;
    for (int i = tid; i < 1024; i += 256) gs[i] = __int_as_float(g_gmax[i]);
    __syncthreads();
    const int w = tid >> 5, lane = tid & 31;
    const int j = blockIdx.x * 8 + w;
    const float* wr = W5 + (size_t)j * 1088 + 64;
    float s = 0.f;
#pragma unroll
    for (int i = 0; i < 32; i++) s = fmaf(wr[lane + 32 * i], gs[lane + 32 * i], s);
#pragma unroll
    for (int m = 16; m; m >>= 1) s += __shfl_xor_sync(0xffffffffu, s, m);
    if (lane == 0) g_c5[j] = s + b5[j];
}

// ============================================================
// Kernel C: blocks 5..8 via HMMA on bf16 planes. cp.async staging.
// CTA = 64 pts, 256 threads (2 M-warps x 4 N-warps).
// block5 bufs: whi32 | z6Hi+4608 (free area behind h planes)
// block6 bufs: whi32 | z6Hi (h dead)
// block7 bufs: z5Hi | z5Hi+9216 (z5 dead), slabs KF=64
// ============================================================
#define SMEM3_FLOATS 56320

__global__ __launch_bounds__(NT, 1) void k_back(
    const float* __restrict__ b6, const float* __restrict__ b7,
    const float* __restrict__ W8, const float* __restrict__ b8,
    float* __restrict__ out) {
    extern __shared__ float sm[];
    uint32_t* z5Hi = (uint32_t*)sm;           // 16640 u32, SAH=520 (SRU=260)
    uint32_t* z5Lo = z5Hi + 16640;
    uint32_t* z6Hi = (uint32_t*)(sm + 33280); // 8448 u32, SAH=264 (SRU=132)
    uint32_t* z6Lo = z6Hi + 8448;
    uint32_t* hHi  = z6Hi;                    // overlay: 2304 u32, SAH=72 (SRU=36)
    uint32_t* hLo  = hHi + 2304;
    uint32_t* whi32 = (uint32_t*)(sm + 50176); // buffer region (6144)
    float* z7 = sm;                           // stride 132 (overlays z5 planes)

    const int tid   = threadIdx.x;
    const int wid   = tid >> 5;
    const int lane  = tid & 31;
    const int pbase = blockIdx.x * 64;

    const uint32_t z5Hi_a = smem_to_u32(z5Hi);
    const uint32_t z5Lo_a = smem_to_u32(z5Lo);
    const uint32_t z6Hi_a = smem_to_u32(z6Hi);
    const uint32_t z6Lo_a = smem_to_u32(z6Lo);
    const uint32_t hHi_a  = smem_to_u32(hHi);
    const uint32_t hLo_a  = smem_to_u32(hLo);
    const uint32_t whi_a  = smem_to_u32(whi32);
    const uint32_t buf5a[2] = { whi_a, z6Hi_a + 4608 * 4 };
    const uint32_t buf6a[2] = { whi_a, z6Hi_a };
    const uint32_t buf7a[2] = { z5Hi_a, z5Hi_a + 9216 * 4 };

    // kick off W5 slab 0 into whi32 immediately
    cpaSlab<6>(buf5a[0], g_w5);
    cpa_commit();

    // copy h planes from pre-split global image
    {
        const uint32_t* hiSrc = g_hp + (size_t)(blockIdx.x >> 1) * 9216 + (blockIdx.x & 1) * 2304;
        const uint4* s0 = (const uint4*)hiSrc;
        const uint4* s1 = (const uint4*)(hiSrc + 4608);
        uint4* d0 = (uint4*)hHi;
        uint4* d1 = (uint4*)hLo;
        for (int i = tid; i < 576; i += NT) { d0[i] = s0[i]; d1[i] = s1[i]; }
    }

    const int m0 = (wid & 1) * 32;   // 2 M-warps
    const int wn = wid >> 1;         // 4 N-warps

    // ---- block5: z5 = relu(h @ W5a^T + c5). 2 N-passes of 256, K=64.
    for (int cc = 0; cc < 2; cc++) {
        float acc[2][8][4];
#pragma unroll
        for (int mi = 0; mi < 2; mi++)
#pragma unroll
            for (int nj = 0; nj < 8; nj++)
#pragma unroll
                for (int q = 0; q < 4; q++) acc[mi][nj][q] = 0.f;
        for (int s = 0; s < 4; s++) {
            int t = cc * 4 + s;
            cpa_wait0();
            __syncthreads();
            if (t + 1 < 8) { cpaSlab<6>(buf5a[(t + 1) & 1], g_w5 + (t + 1) * 6144); cpa_commit(); }
            else           { cpaSlab<6>(buf6a[0], g_w6); cpa_commit(); }  // chain W6 slab 0
            uint32_t whi = buf5a[t & 1];
            gemm_kstep_p<4>(hHi_a, hLo_a, 72, m0, whi, whi + 3072 * 4, 24,
                            wn * 64, 0, s * 16, lane, acc);
        }
        epi_store_p<8>(z5Hi, z5Lo, 260, m0, cc * 256 + wn * 64, g_c5, acc, lane);
    }

    // ---- block6: z6 = relu(z5 @ W6^T + b6). N=256, K=512. cp.async ping-pong.
    {
        float acc[2][8][4];
#pragma unroll
        for (int mi = 0; mi < 2; mi++)
#pragma unroll
            for (int nj = 0; nj < 8; nj++)
#pragma unroll
                for (int q = 0; q < 4; q++) acc[mi][nj][q] = 0.f;
        for (int s = 0; s < 32; s++) {
            cpa_wait0();
            __syncthreads();
            if (s + 1 < 32) { cpaSlab<6>(buf6a[(s + 1) & 1], g_w6 + (s + 1) * 6144); cpa_commit(); }
            uint32_t whi = buf6a[s & 1];
            gemm_kstep_p<4>(z5Hi_a, z5Lo_a, 520, m0, whi, whi + 3072 * 4, 24,
                            wn * 64, 0, s * 16, lane, acc);
        }
        __syncthreads();   // all reads of buffers and z5 done
        cpaSlab<9>(buf7a[0], g_w7);   // W7 slab 0 into z5 region (now dead); overlaps epi
        cpa_commit();
        epi_store_p<8>(z6Hi, z6Lo, 132, m0, wn * 64, b6, acc, lane);
    }

    // ---- block7: z7 = relu(z6 @ W7^T + b7). N=128, K=256, 4 stages of KF=64.
    {
        float acc[2][4][4];
#pragma unroll
        for (int mi = 0; mi < 2; mi++)
#pragma unroll
            for (int nj = 0; nj < 4; nj++)
#pragma unroll
                for (int q = 0; q < 4; q++) acc[mi][nj][q] = 0.f;
        for (int s = 0; s < 4; s++) {
            cpa_wait0();
            __syncthreads();   // also orders z6 epilogue before first gemm
            if (s + 1 < 4) { cpaSlab<9>(buf7a[(s + 1) & 1], g_w7 + (s + 1) * 9216); cpa_commit(); }
            uint32_t whi = buf7a[s & 1];
#pragma unroll
            for (int q = 0; q < 4; q++)
                gemm_kstep_p<2>(z6Hi_a, z6Lo_a, 264, m0, whi, whi + 4608 * 4, 72,
                                wn * 32, q * 16, s * 64 + q * 16, lane, acc);
        }
        __syncthreads();   // all buffer reads done; safe to overlay z7 fp32
        epi_store<4>(z7, 132, m0, wn * 32, b7, acc, lane);
    }
    __syncthreads();

    // ---- block8: out = z7 @ W8^T + b8 (no relu)
    if (tid < 64) {
        const float* zr = z7 + tid * 132;
        float s = __ldg(b8);
#pragma unroll 8
        for (int k = 0; k < 128; k++) s = fmaf(zr[k], __ldg(W8 + k), s);
        out[pbase + tid] = s;
    }
}

// ============================================================
extern "C" void kernel_launch(void* const* d_in, const int* in_sizes, int n_in,
                              void* d_out, int out_size) {
    const float* x  = (const float*)d_in[0];
    const float* W1 = (const float*)d_in[1];  const float* b1 = (const float*)d_in[2];
    const float* W2 = (const float*)d_in[3];  const float* b2 = (const float*)d_in[4];
    const float* W3 = (const float*)d_in[5];  const float* b3 = (const float*)d_in[6];
    const float* W4 = (const float*)d_in[7];  const float* b4 = (const float*)d_in[8];
    const float* W5 = (const float*)d_in[9];  const float* b5 = (const float*)d_in[10];
    const float* W6 = (const float*)d_in[11]; const float* b6 = (const float*)d_in[12];
    const float* W7 = (const float*)d_in[13]; const float* b7 = (const float*)d_in[14];
    const float* W8 = (const float*)d_in[15]; const float* b8 = (const float*)d_in[16];
    float* out = (float*)d_out;

    const int n = in_sizes[0] / 3;  // 65536

    const int smem1 = SMEM1_FLOATS * (int)sizeof(float);
    const int smem3 = SMEM3_FLOATS * (int)sizeof(float);
    cudaFuncSetAttribute(k_front, cudaFuncAttributeMaxDynamicSharedMemorySize, smem1);
    cudaFuncSetAttribute(k_back,  cudaFuncAttributeMaxDynamicSharedMemorySize, smem3);

    k_prep<<<128, 256>>>(W2, W3, W4, W5, W6, W7);
    k_front<<<n / 128, NT, smem1>>>(x, W1, b1, b2, b3, b4);
    k_c5<<<64, 256>>>(W5, b5);
    k_back<<<n / 64, NT, smem3>>>(b6, b7, W8, b8, out);
}

// round 16
// speedup vs baseline: 1.0922x; 1.0397x over previous
#include <cuda_runtime.h>
#include <cuda_bf16.h>
#include <cstdint>

#define NT 256

// -------- persistent device scratch (no allocs allowed) --------
__device__ int   g_gmax[1024];      // global max-pool accumulator (float bits, >=0)
__device__ float g_c5[512];         // c5 = b5 + W5[:,64:] @ g

// h (block2 output) as bf16 hi/lo plane images: per 128-pt front CTA,
// [128 rows][36 u32] hi plane (4608 u32) || lo plane (4608 u32)
__device__ __align__(16) uint32_t g_hp[512 * 9216];

// pre-split bf16 weight planes, stored as exact smem slab images (hi plane || lo plane)
__device__ __align__(16) uint32_t g_w2[4608];        // block2: [64][36u32] x2
__device__ __align__(16) uint32_t g_w3[9216];        // block3: [128][36u32] x2
__device__ __align__(16) uint32_t g_w4[16 * 9216];   // block4: 16 slabs [128][36u32] x2
__device__ __align__(16) uint32_t g_w5[8 * 6144];    // block5: 8 slabs [256][12u32] x2
__device__ __align__(16) uint32_t g_w6[16 * 10240];  // block6: 16 slabs [256][20u32] x2 (KF=32)
__device__ __align__(16) uint32_t g_w7[4 * 9216];    // block7: 4 slabs [128][36u32] x2 (KF=64)

__device__ __forceinline__ float frelu(float v) { return v > 0.f ? v : 0.f; }

// ============================================================
// HMMA (mma.sync) machinery — compiles at plain sm_103 target.
// ============================================================
__device__ __forceinline__ void mma16816(float* c, const uint32_t* a, const uint32_t* b) {
    asm volatile(
        "mma.sync.aligned.m16n8k16.row.col.f32.bf16.bf16.f32 "
        "{%0,%1,%2,%3}, {%4,%5,%6,%7}, {%8,%9}, {%0,%1,%2,%3};"
        : "+f"(c[0]), "+f"(c[1]), "+f"(c[2]), "+f"(c[3])
        : "r"(a[0]), "r"(a[1]), "r"(a[2]), "r"(a[3]), "r"(b[0]), "r"(b[1]));
}
__device__ __forceinline__ void ldsm4(uint32_t r[4], uint32_t addr) {
    asm volatile("ldmatrix.sync.aligned.m8n8.x4.shared.b16 {%0,%1,%2,%3}, [%4];"
                 : "=r"(r[0]), "=r"(r[1]), "=r"(r[2]), "=r"(r[3]) : "r"(addr));
}
__device__ __forceinline__ uint32_t smem_to_u32(const void* p) {
    uint32_t a;
    asm("{ .reg .u64 t; cvta.to.shared.u64 t, %1; cvt.u32.u64 %0, t; }" : "=r"(a) : "l"(p));
    return a;
}

// ---- cp.async staging (no registers, no STS) ----
__device__ __forceinline__ void cpa16(uint32_t daddr, const void* g) {
    asm volatile("cp.async.cg.shared.global [%0], [%1], 16;" :: "r"(daddr), "l"(g));
}
__device__ __forceinline__ void cpa_commit() {
    asm volatile("cp.async.commit_group;" ::: "memory");
}
__device__ __forceinline__ void cpa_wait0() {
    asm volatile("cp.async.wait_group 0;" ::: "memory");
}
// copy NV*NT uint4 (NV*NT*4 u32) from src to smem byte-address dbase
template <int NV>
__device__ __forceinline__ void cpaSlab(uint32_t dbase, const uint32_t* __restrict__ src) {
#pragma unroll
    for (int j = 0; j < NV; j++) {
        int idx = threadIdx.x + j * NT;
        cpa16(dbase + (uint32_t)idx * 16, src + (size_t)idx * 4);
    }
}

// split a float2 into packed bf16x2 hi and lo (residual) parts.
__device__ __forceinline__ void split2(float2 v, uint32_t& hi, uint32_t& lo) {
    uint32_t h;
    asm("cvt.rn.bf16x2.f32 %0, %1, %2;" : "=r"(h) : "f"(v.y), "f"(v.x));
    float h0 = __uint_as_float(h << 16);
    float h1 = __uint_as_float(h & 0xFFFF0000u);
    float l0 = v.x - h0, l1 = v.y - h1;
    asm("cvt.rn.bf16x2.f32 %0, %1, %2;" : "=r"(lo) : "f"(l1), "f"(l0));
    hi = h;
}

// ldmatrix.x4 A-fragment load from a bf16 plane (row-major, SAH halves/row).
__device__ __forceinline__ void ldAm(uint32_t r[4], uint32_t plane, int SAH,
                                     int row0, int kabs, int lane) {
    int j = lane >> 3, rr = lane & 7;
    int row = row0 + ((j & 1) << 3) + rr;
    int col = kabs + ((j >> 1) << 3);
    ldsm4(r, plane + (uint32_t)(row * SAH + col) * 2);
}

// One k16 step of warp GEMM on bf16 planes: 32 rows x (NTILES*16) cols, 3-term split.
template <int NTILES>
__device__ __forceinline__ void gemm_kstep_p(uint32_t aHi, uint32_t aLo, int SAH, int m0,
                                             uint32_t whi, uint32_t wlo, int SWB,
                                             int n0loc, int k0loc, int kabs, int lane,
                                             float acc[2][NTILES * 2][4]) {
    uint32_t ahi[2][4], alo[2][4];
    ldAm(ahi[0], aHi, SAH, m0,      kabs, lane);
    ldAm(ahi[1], aHi, SAH, m0 + 16, kabs, lane);
    ldAm(alo[0], aLo, SAH, m0,      kabs, lane);
    ldAm(alo[1], aLo, SAH, m0 + 16, kabs, lane);
    uint32_t bh[NTILES][4], bl[NTILES][4];
    const int nl = n0loc + (lane & 7) + ((lane >> 4) << 3);
    const int kk = k0loc + (((lane >> 3) & 1) << 3);
#pragma unroll
    for (int nt = 0; nt < NTILES; nt++) {
        uint32_t off = (uint32_t)((nl + nt * 16) * SWB + kk) * 2;
        ldsm4(bh[nt], whi + off);
        ldsm4(bl[nt], wlo + off);
    }
#pragma unroll
    for (int mi = 0; mi < 2; mi++)
#pragma unroll
        for (int nt = 0; nt < NTILES; nt++) {
            mma16816(acc[mi][2 * nt],     ahi[mi], &bh[nt][0]);
            mma16816(acc[mi][2 * nt + 1], ahi[mi], &bh[nt][2]);
        }
#pragma unroll
    for (int mi = 0; mi < 2; mi++)
#pragma unroll
        for (int nt = 0; nt < NTILES; nt++) {
            mma16816(acc[mi][2 * nt],     ahi[mi], &bl[nt][0]);
            mma16816(acc[mi][2 * nt + 1], ahi[mi], &bl[nt][2]);
        }
#pragma unroll
    for (int mi = 0; mi < 2; mi++)
#pragma unroll
        for (int nt = 0; nt < NTILES; nt++) {
            mma16816(acc[mi][2 * nt],     alo[mi], &bh[nt][0]);
            mma16816(acc[mi][2 * nt + 1], alo[mi], &bh[nt][2]);
        }
}

// Epilogue: relu(acc + bias) -> bf16 hi/lo planes (u32-addressed, SRU u32/row).
template <int NJ>
__device__ __forceinline__ void epi_store_p(uint32_t* __restrict__ hiP,
                                            uint32_t* __restrict__ loP, int SRU,
                                            int m0, int nbase, const float* __restrict__ bias,
                                            float acc[2][NJ][4], int lane) {
    int g = lane >> 2, t = lane & 3;
#pragma unroll
    for (int mi = 0; mi < 2; mi++)
#pragma unroll
        for (int nj = 0; nj < NJ; nj++) {
            int col = nbase + nj * 8 + 2 * t;
            float2 b = __ldg((const float2*)(bias + col));
            int row = m0 + mi * 16 + g;
            uint32_t h0, l0, h1, l1;
            split2(make_float2(frelu(acc[mi][nj][0] + b.x), frelu(acc[mi][nj][1] + b.y)), h0, l0);
            split2(make_float2(frelu(acc[mi][nj][2] + b.x), frelu(acc[mi][nj][3] + b.y)), h1, l1);
            int cp = col >> 1;
            hiP[row * SRU + cp] = h0;       loP[row * SRU + cp] = l0;
            hiP[(row + 8) * SRU + cp] = h1; loP[(row + 8) * SRU + cp] = l1;
        }
}
// Epilogue: relu(acc + bias) -> fp32 smem (for block7 -> block8)
template <int NJ>
__device__ __forceinline__ void epi_store(float* __restrict__ Z, int SZ, int m0, int nbase,
                                          const float* __restrict__ bias,
                                          float acc[2][NJ][4], int lane) {
    int g = lane >> 2, t = lane & 3;
#pragma unroll
    for (int mi = 0; mi < 2; mi++)
#pragma unroll
        for (int nj = 0; nj < NJ; nj++) {
            int col = nbase + nj * 8 + 2 * t;
            float2 b = __ldg((const float2*)(bias + col));
            int row = m0 + mi * 16 + g;
            *(float2*)(Z + (size_t)row * SZ + col) =
                make_float2(frelu(acc[mi][nj][0] + b.x), frelu(acc[mi][nj][1] + b.y));
            *(float2*)(Z + (size_t)(row + 8) * SZ + col) =
                make_float2(frelu(acc[mi][nj][2] + b.x), frelu(acc[mi][nj][3] + b.y));
        }
}

// ============================================================
// k_prep: split MMA weights into bf16 hi/lo global slab images.
// Also resets g_gmax (merged k_init).
// ============================================================
__global__ void k_prep(const float* __restrict__ W2, const float* __restrict__ W3,
                       const float* __restrict__ W4, const float* __restrict__ W5,
                       const float* __restrict__ W6, const float* __restrict__ W7) {
    const int tid = blockIdx.x * blockDim.x + threadIdx.x;
    const int nth = gridDim.x * blockDim.x;
    if (tid < 1024) g_gmax[tid] = 0;
    // block2: [64 rows][36 u32], K=64
    for (int i = tid; i < 64 * 36; i += nth) {
        int c = i / 36, k2 = i % 36;
        uint32_t hi = 0, lo = 0;
        if (k2 < 32) {
            const float* p = W2 + (size_t)c * 64 + 2 * k2;
            split2(make_float2(p[0], p[1]), hi, lo);
        }
        g_w2[c * 36 + k2] = hi;
        g_w2[2304 + c * 36 + k2] = lo;
    }
    // block3: [128 rows][36 u32], K=64
    for (int i = tid; i < 128 * 36; i += nth) {
        int c = i / 36, k2 = i % 36;
        uint32_t hi = 0, lo = 0;
        if (k2 < 32) {
            const float* p = W3 + (size_t)c * 64 + 2 * k2;
            split2(make_float2(p[0], p[1]), hi, lo);
        }
        g_w3[c * 36 + k2] = hi;
        g_w3[4608 + c * 36 + k2] = lo;
    }
    // block4: 16 slabs [128 rows][36 u32] (KF=64 -> 32 data u32 + 4 pad)
    for (int i = tid; i < 16 * 128 * 36; i += nth) {
        int t = i / (128 * 36), r = i % (128 * 36);
        int c = r / 36, k2 = r % 36;
        uint32_t hi = 0, lo = 0;
        if (k2 < 32) {
            const float* p = W4 + (size_t)((t >> 1) * 128 + c) * 128 + (t & 1) * 64 + 2 * k2;
            split2(make_float2(p[0], p[1]), hi, lo);
        }
        g_w4[t * 9216 + c * 36 + k2] = hi;
        g_w4[t * 9216 + 4608 + c * 36 + k2] = lo;
    }
    // block5: 8 slabs [256][12 u32] (KF=16 -> 8 data + 4 pad)
    for (int i = tid; i < 8 * 256 * 12; i += nth) {
        int t = i / (256 * 12), r = i % (256 * 12);
        int c = r / 12, k2 = r % 12;
        uint32_t hi = 0, lo = 0;
        if (k2 < 8) {
            const float* p = W5 + (size_t)((t >> 2) * 256 + c) * 1088 + (t & 3) * 16 + 2 * k2;
            split2(make_float2(p[0], p[1]), hi, lo);
        }
        g_w5[t * 6144 + c * 12 + k2] = hi;
        g_w5[t * 6144 + 3072 + c * 12 + k2] = lo;
    }
    // block6: 16 slabs [256][20 u32] (KF=32 -> 16 data + 4 pad)
    for (int i = tid; i < 16 * 256 * 20; i += nth) {
        int t = i / (256 * 20), r = i % (256 * 20);
        int c = r / 20, k2 = r % 20;
        uint32_t hi = 0, lo = 0;
        if (k2 < 16) {
            const float* p = W6 + (size_t)c * 512 + t * 32 + 2 * k2;
            split2(make_float2(p[0], p[1]), hi, lo);
        }
        g_w6[t * 10240 + c * 20 + k2] = hi;
        g_w6[t * 10240 + 5120 + c * 20 + k2] = lo;
    }
    // block7: 4 slabs [128][36 u32] (KF=64 -> 32 data + 4 pad)
    for (int i = tid; i < 4 * 128 * 36; i += nth) {
        int t = i / (128 * 36), r = i % (128 * 36);
        int c = r / 36, k2 = r % 36;
        uint32_t hi = 0, lo = 0;
        if (k2 < 32) {
            const float* p = W7 + (size_t)c * 256 + t * 64 + 2 * k2;
            split2(make_float2(p[0], p[1]), hi, lo);
        }
        g_w7[t * 9216 + c * 36 + k2] = hi;
        g_w7[t * 9216 + 4608 + c * 36 + k2] = lo;
    }
}

// ============================================================
// Kernel A: block1 SIMT-lite + blocks 2,3,4 via HMMA on bf16 planes.
// CTA = 128 points, 256 threads (4 M-warps x 2 N-warps).
// block4: cp.async ping-pong, buf0 = w4s region, buf1 = a1/w3 region.
// ============================================================
#define SMEM1_FLOATS 51328

__global__ __launch_bounds__(NT, 1) void k_front(
    const float* __restrict__ x,
    const float* __restrict__ W1, const float* __restrict__ b1,
    const float* __restrict__ b2, const float* __restrict__ b3,
    const float* __restrict__ b4) {
    extern __shared__ float sm[];
    uint32_t* u = (uint32_t*)sm;
    uint32_t* a1Hi = u;            // SRU 36
    uint32_t* a1Lo = u + 4608;
    uint32_t* w3s  = u;            // overlay (hi @0, lo @4608); later buf1
    uint32_t* hHi  = u + 9216;     // SRU 36
    uint32_t* hLo  = u + 13824;
    uint32_t* aHi  = u + 18432;    // SRU 68
    uint32_t* aLo  = u + 27136;
    uint32_t* buf0 = u + 35840;    // block4 buffer 0 (9216)
    uint32_t* w2s  = u + 45056;    // 4608 (hi 2304 || lo 2304)
    int*   gmax = (int*)(u + 49664);
    float* cst  = sm + 50688;
    float* w1s = cst;          // 192
    float* b1s = cst + 192;    // 64
    float* xs  = cst + 256;    // 384

    const int tid   = threadIdx.x;
    const int wid   = tid >> 5;
    const int lane  = tid & 31;
    const int pbase = blockIdx.x * 128;

    const uint32_t buf4a[2] = { smem_to_u32(buf0), smem_to_u32(u) };  // buf1 = a1/w3 region

    // kick off W4 slab 0 into buf0 immediately (region untouched until block4)
    cpaSlab<9>(buf4a[0], g_w4);
    cpa_commit();

    for (int i = tid; i < 1024; i += NT) gmax[i] = 0;
    for (int i = tid; i < 192; i += NT) w1s[i] = W1[i];
    for (int i = tid; i < 64; i += NT) b1s[i] = b1[i];
    for (int i = tid; i < 384; i += NT) xs[i] = x[pbase * 3 + i];
    for (int i = tid; i < 1152; i += NT)
        ((uint4*)w2s)[i] = ((const uint4*)g_w2)[i];
    __syncthreads();

    // ---- block1: a1 = relu(x @ W1^T + b1) -> a1 planes
    for (int idx = tid; idx < 128 * 32; idx += NT) {
        int p = idx >> 5, c2 = idx & 31;
        int c = 2 * c2;
        float v0 = fmaf(xs[p * 3 + 2], w1s[c * 3 + 2],
                   fmaf(xs[p * 3 + 1], w1s[c * 3 + 1],
                   fmaf(xs[p * 3 + 0], w1s[c * 3 + 0], b1s[c])));
        float v1 = fmaf(xs[p * 3 + 2], w1s[c * 3 + 5],
                   fmaf(xs[p * 3 + 1], w1s[c * 3 + 4],
                   fmaf(xs[p * 3 + 0], w1s[c * 3 + 3], b1s[c + 1])));
        uint32_t hi, lo;
        split2(make_float2(frelu(v0), frelu(v1)), hi, lo);
        a1Hi[p * 36 + c2] = hi;
        a1Lo[p * 36 + c2] = lo;
    }
    __syncthreads();

    const uint32_t a1Hi_a = smem_to_u32(a1Hi);
    const uint32_t a1Lo_a = smem_to_u32(a1Lo);
    const uint32_t hHi_a  = smem_to_u32(hHi);
    const uint32_t hLo_a  = smem_to_u32(hLo);
    const uint32_t aHi_a  = smem_to_u32(aHi);
    const uint32_t aLo_a  = smem_to_u32(aLo);
    const uint32_t w2hi_a = smem_to_u32(w2s);
    const uint32_t w3hi_a = smem_to_u32(w3s);
    const int m0 = (wid & 3) * 32;   // 4 M-warps
    const int wn = wid >> 2;         // 2 N-warps

    // ---- block2: h = relu(a1 @ W2^T + b2) -> h planes, K=64, N=64 (32 cols/warp)
    {
        float acc[2][4][4];
#pragma unroll
        for (int mi = 0; mi < 2; mi++)
#pragma unroll
            for (int nj = 0; nj < 4; nj++)
#pragma unroll
                for (int q = 0; q < 4; q++) acc[mi][nj][q] = 0.f;
#pragma unroll
        for (int s = 0; s < 4; s++)
            gemm_kstep_p<2>(a1Hi_a, a1Lo_a, 72, m0, w2hi_a, w2hi_a + 2304 * 4, 72,
                            wn * 32, s * 16, s * 16, lane, acc);
        epi_store_p<4>(hHi, hLo, 36, m0, wn * 32, b2, acc, lane);
    }
    __syncthreads();

    // h planes -> global image; w3 image -> smem (a1 dead)
    {
        uint4* dst = (uint4*)(g_hp + (size_t)blockIdx.x * 9216);
        const uint4* srcH = (const uint4*)hHi;
        for (int i = tid; i < 2304; i += NT) dst[i] = srcH[i];
        for (int i = tid; i < 2304; i += NT)
            ((uint4*)w3s)[i] = ((const uint4*)g_w3)[i];
    }
    __syncthreads();

    // ---- block3: a3 = relu(h @ W3^T + b3) -> a planes, K=64, N=128 (64 cols/warp)
    {
        float acc[2][8][4];
#pragma unroll
        for (int mi = 0; mi < 2; mi++)
#pragma unroll
            for (int nj = 0; nj < 8; nj++)
#pragma unroll
                for (int q = 0; q < 4; q++) acc[mi][nj][q] = 0.f;
#pragma unroll
        for (int s = 0; s < 4; s++)
            gemm_kstep_p<4>(hHi_a, hLo_a, 72, m0, w3hi_a, w3hi_a + 4608 * 4, 72,
                            wn * 64, s * 16, s * 16, lane, acc);
        epi_store_p<8>(aHi, aLo, 68, m0, wn * 64, b3, acc, lane);
    }
    // no sync — block4 stage 0's sync orders epi writes and w3 reads.

    // ---- block4: 16 slab-stages (2 per 128-ch chunk), cp.async ping-pong.
    const int n0 = wn * 64;
    for (int cc = 0; cc < 8; cc++) {
        float acc[2][8][4];
#pragma unroll
        for (int mi = 0; mi < 2; mi++)
#pragma unroll
            for (int nj = 0; nj < 8; nj++)
#pragma unroll
                for (int q = 0; q < 4; q++) acc[mi][nj][q] = 0.f;

        for (int s = 0; s < 2; s++) {
            int t = cc * 2 + s;
            cpa_wait0();
            __syncthreads();
            if (t + 1 < 16) { cpaSlab<9>(buf4a[(t + 1) & 1], g_w4 + (t + 1) * 9216); cpa_commit(); }
            uint32_t whi = buf4a[t & 1];
#pragma unroll
            for (int q = 0; q < 4; q++)
                gemm_kstep_p<4>(aHi_a, aLo_a, 136, m0, whi, whi + 4608 * 4, 72,
                                n0, q * 16, s * 64 + q * 16, lane, acc);
        }

        float m0v[8], m1v[8];
#pragma unroll
        for (int nj = 0; nj < 8; nj++) {
            m0v[nj] = fmaxf(fmaxf(acc[0][nj][0], acc[0][nj][2]),
                            fmaxf(acc[1][nj][0], acc[1][nj][2]));
            m1v[nj] = fmaxf(fmaxf(acc[0][nj][1], acc[0][nj][3]),
                            fmaxf(acc[1][nj][1], acc[1][nj][3]));
        }
#pragma unroll
        for (int m = 4; m < 32; m <<= 1)
#pragma unroll
            for (int nj = 0; nj < 8; nj++) {
                m0v[nj] = fmaxf(m0v[nj], __shfl_xor_sync(0xffffffffu, m0v[nj], m));
                m1v[nj] = fmaxf(m1v[nj], __shfl_xor_sync(0xffffffffu, m1v[nj], m));
            }
        if ((lane >> 2) == 0) {
            int t = lane & 3;
#pragma unroll
            for (int nj = 0; nj < 8; nj++) {
                int col = cc * 128 + n0 + nj * 8 + 2 * t;
                float2 b = __ldg((const float2*)(b4 + col));
                atomicMax(&gmax[col],     __float_as_int(frelu(m0v[nj] + b.x)));
                atomicMax(&gmax[col + 1], __float_as_int(frelu(m1v[nj] + b.y)));
            }
        }
    }
    __syncthreads();
    for (int i = tid; i < 1024; i += NT) atomicMax(&g_gmax[i], gmax[i]);
}

// ============================================================
// Kernel B: c5[j] = b5[j] + sum_i W5[j][64+i] * g[i]
// ============================================================
__global__ void k_c5(const float* __restrict__ W5, const float* __restrict__ b5) {
    __shared__ float gs[1024];
    const int tid = threadIdx.x;
    for (int i = tid; i < 1024; i += 256) gs[i] = __int_as_float(g_gmax[i]);
    __syncthreads();
    const int w = tid >> 5, lane = tid & 31;
    const int j = blockIdx.x * 8 + w;
    const float* wr = W5 + (size_t)j * 1088 + 64;
    float s = 0.f;
#pragma unroll
    for (int i = 0; i < 32; i++) s = fmaf(wr[lane + 32 * i], gs[lane + 32 * i], s);
#pragma unroll
    for (int m = 16; m; m >>= 1) s += __shfl_xor_sync(0xffffffffu, s, m);
    if (lane == 0) g_c5[j] = s + b5[j];
}

// ============================================================
// Kernel C: blocks 5..8 via HMMA on bf16 planes. cp.async staging.
// CTA = 64 pts, 256 threads (2 M-warps x 4 N-warps).
// u32 offsets: z5 planes 0..33280 | z6 region 33280..50176 | whi 50176..56320
// block5 bufs (6144): @50176 | @37888          (h planes live at 33280..37888)
// block6 bufs (10240, KF=32): @44032 | @33280  (h dead; slab0 chained @44032)
// block7 bufs (9216, KF=64): @0 | @9216        (z5 dead)
// ============================================================
#define SMEM3_FLOATS 56320

__global__ __launch_bounds__(NT, 1) void k_back(
    const float* __restrict__ b6, const float* __restrict__ b7,
    const float* __restrict__ W8, const float* __restrict__ b8,
    float* __restrict__ out) {
    extern __shared__ float sm[];
    uint32_t* ub = (uint32_t*)sm;
    uint32_t* z5Hi = ub;                 // 16640 u32, SAH=520 (SRU=260)
    uint32_t* z5Lo = z5Hi + 16640;
    uint32_t* z6Hi = ub + 33280;         // 8448 u32, SAH=264 (SRU=132)
    uint32_t* z6Lo = z6Hi + 8448;
    uint32_t* hHi  = z6Hi;               // overlay: 2304 u32, SAH=72 (SRU=36)
    uint32_t* hLo  = hHi + 2304;
    float* z7 = sm;                      // stride 132 (overlays z5 planes)

    const int tid   = threadIdx.x;
    const int wid   = tid >> 5;
    const int lane  = tid & 31;
    const int pbase = blockIdx.x * 64;

    const uint32_t base_a = smem_to_u32(ub);
    const uint32_t z5Hi_a = base_a;
    const uint32_t z5Lo_a = base_a + 16640 * 4;
    const uint32_t z6Hi_a = base_a + 33280 * 4;
    const uint32_t z6Lo_a = z6Hi_a + 8448 * 4;
    const uint32_t hHi_a  = z6Hi_a;
    const uint32_t hLo_a  = hHi_a + 2304 * 4;
    const uint32_t buf5a[2] = { base_a + 50176 * 4, base_a + 37888 * 4 };
    const uint32_t buf6a[2] = { base_a + 44032 * 4, base_a + 33280 * 4 };
    const uint32_t buf7a[2] = { base_a, base_a + 9216 * 4 };

    // kick off W5 slab 0
    cpaSlab<6>(buf5a[0], g_w5);
    cpa_commit();

    // copy h planes from pre-split global image
    {
        const uint32_t* hiSrc = g_hp + (size_t)(blockIdx.x >> 1) * 9216 + (blockIdx.x & 1) * 2304;
        const uint4* s0 = (const uint4*)hiSrc;
        const uint4* s1 = (const uint4*)(hiSrc + 4608);
        uint4* d0 = (uint4*)hHi;
        uint4* d1 = (uint4*)hLo;
        for (int i = tid; i < 576; i += NT) { d0[i] = s0[i]; d1[i] = s1[i]; }
    }

    const int m0 = (wid & 1) * 32;   // 2 M-warps
    const int wn = wid >> 1;         // 4 N-warps

    // ---- block5: z5 = relu(h @ W5a^T + c5). 2 N-passes of 256, K=64.
    for (int cc = 0; cc < 2; cc++) {
        float acc[2][8][4];
#pragma unroll
        for (int mi = 0; mi < 2; mi++)
#pragma unroll
            for (int nj = 0; nj < 8; nj++)
#pragma unroll
                for (int q = 0; q < 4; q++) acc[mi][nj][q] = 0.f;
        for (int s = 0; s < 4; s++) {
            int t = cc * 4 + s;
            cpa_wait0();
            __syncthreads();
            if (t + 1 < 8) { cpaSlab<6>(buf5a[(t + 1) & 1], g_w5 + (t + 1) * 6144); cpa_commit(); }
            else           { cpaSlab<10>(buf6a[0], g_w6); cpa_commit(); }  // chain W6 slab 0
            uint32_t whi = buf5a[t & 1];
            gemm_kstep_p<4>(hHi_a, hLo_a, 72, m0, whi, whi + 3072 * 4, 24,
                            wn * 64, 0, s * 16, lane, acc);
        }
        epi_store_p<8>(z5Hi, z5Lo, 260, m0, cc * 256 + wn * 64, g_c5, acc, lane);
    }

    // ---- block6: z6 = relu(z5 @ W6^T + b6). N=256, K=512. 16 stages of KF=32.
    {
        float acc[2][8][4];
#pragma unroll
        for (int mi = 0; mi < 2; mi++)
#pragma unroll
            for (int nj = 0; nj < 8; nj++)
#pragma unroll
                for (int q = 0; q < 4; q++) acc[mi][nj][q] = 0.f;
        for (int s = 0; s < 16; s++) {
            cpa_wait0();
            __syncthreads();
            if (s + 1 < 16) { cpaSlab<10>(buf6a[(s + 1) & 1], g_w6 + (s + 1) * 10240); cpa_commit(); }
            uint32_t whi = buf6a[s & 1];
#pragma unroll
            for (int q = 0; q < 2; q++)
                gemm_kstep_p<4>(z5Hi_a, z5Lo_a, 520, m0, whi, whi + 5120 * 4, 40,
                                wn * 64, q * 16, s * 32 + q * 16, lane, acc);
        }
        __syncthreads();   // all reads of buffers and z5 done
        cpaSlab<9>(buf7a[0], g_w7);   // W7 slab 0 into z5 region (now dead); overlaps epi
        cpa_commit();
        epi_store_p<8>(z6Hi, z6Lo, 132, m0, wn * 64, b6, acc, lane);
    }

    // ---- block7: z7 = relu(z6 @ W7^T + b7). N=128, K=256, 4 stages of KF=64.
    {
        float acc[2][4][4];
#pragma unroll
        for (int mi = 0; mi < 2; mi++)
#pragma unroll
            for (int nj = 0; nj < 4; nj++)
#pragma unroll
                for (int q = 0; q < 4; q++) acc[mi][nj][q] = 0.f;
        for (int s = 0; s < 4; s++) {
            cpa_wait0();
            __syncthreads();   // also orders z6 epilogue before first gemm
            if (s + 1 < 4) { cpaSlab<9>(buf7a[(s + 1) & 1], g_w7 + (s + 1) * 9216); cpa_commit(); }
            uint32_t whi = buf7a[s & 1];
#pragma unroll
            for (int q = 0; q < 4; q++)
                gemm_kstep_p<2>(z6Hi_a, z6Lo_a, 264, m0, whi, whi + 4608 * 4, 72,
                                wn * 32, q * 16, s * 64 + q * 16, lane, acc);
        }
        __syncthreads();   // all buffer reads done; safe to overlay z7 fp32
        epi_store<4>(z7, 132, m0, wn * 32, b7, acc, lane);
    }
    __syncthreads();

    // ---- block8: out = z7 @ W8^T + b8 (no relu)
    if (tid < 64) {
        const float* zr = z7 + tid * 132;
        float s = __ldg(b8);
#pragma unroll 8
        for (int k = 0; k < 128; k++) s = fmaf(zr[k], __ldg(W8 + k), s);
        out[pbase + tid] = s;
    }
}

// ============================================================
extern "C" void kernel_launch(void* const* d_in, const int* in_sizes, int n_in,
                              void* d_out, int out_size) {
    const float* x  = (const float*)d_in[0];
    const float* W1 = (const float*)d_in[1];  const float* b1 = (const float*)d_in[2];
    const float* W2 = (const float*)d_in[3];  const float* b2 = (const float*)d_in[4];
    const float* W3 = (const float*)d_in[5];  const float* b3 = (const float*)d_in[6];
    const float* W4 = (const float*)d_in[7];  const float* b4 = (const float*)d_in[8];
    const float* W5 = (const float*)d_in[9];  const float* b5 = (const float*)d_in[10];
    const float* W6 = (const float*)d_in[11]; const float* b6 = (const float*)d_in[12];
    const float* W7 = (const float*)d_in[13]; const float* b7 = (const float*)d_in[14];
    const float* W8 = (const float*)d_in[15]; const float* b8 = (const float*)d_in[16];
    float* out = (float*)d_out;

    const int n = in_sizes[0] / 3;  // 65536

    const int smem1 = SMEM1_FLOATS * (int)sizeof(float);
    const int smem3 = SMEM3_FLOATS * (int)sizeof(float);
    cudaFuncSetAttribute(k_front, cudaFuncAttributeMaxDynamicSharedMemorySize, smem1);
    cudaFuncSetAttribute(k_back,  cudaFuncAttributeMaxDynamicSharedMemorySize, smem3);

    k_prep<<<128, 256>>>(W2, W3, W4, W5, W6, W7);
    k_front<<<n / 128, NT, smem1>>>(x, W1, b1, b2, b3, b4);
    k_c5<<<64, 256>>>(W5, b5);
    k_back<<<n / 64, NT, smem3>>>(b6, b7, W8, b8, out);
}